// round 6
// baseline (speedup 1.0000x reference)
#include <cuda_runtime.h>

#define HH 2048
#define WW 2048
#define W4 (WW/4)
#define HWN (HH*WW)
#define HWN4 (HWN/4)
#define RAD 10
#define SEG 8
#define THR 1e-3f
#define EPSF 1e-9f
#define SVW 544   // 12 halo + 512 strip + 12 halo + 8 pad (floats)

__device__ double g_acc[8];        // phase-1 reduction channels (self-resetting)
__device__ double g_loss;          // loss accumulator (self-resetting)
__device__ unsigned g_tickA;       // ticket for phase-1 finalize
__device__ unsigned g_tickB;       // ticket for phase-2 finalize
__device__ float g_v[4];

// ---- float4 helpers --------------------------------------------------------
__device__ __forceinline__ float4 f4z() { return make_float4(0.f, 0.f, 0.f, 0.f); }
__device__ __forceinline__ float4 f4add(float4 a, float4 b) {
    return make_float4(a.x + b.x, a.y + b.y, a.z + b.z, a.w + b.w);
}
__device__ __forceinline__ float4 f4sub(float4 a, float4 b) {
    return make_float4(a.x - b.x, a.y - b.y, a.z - b.z, a.w - b.w);
}
__device__ __forceinline__ float4 f4mul(float4 a, float4 b) {
    return make_float4(a.x * b.x, a.y * b.y, a.z * b.z, a.w * b.w);
}
__device__ __forceinline__ float4 f4mask(float4 i) {
    return make_float4(i.x > THR ? 1.f : 0.f, i.y > THR ? 1.f : 0.f,
                       i.z > THR ? 1.f : 0.f, i.w > THR ? 1.f : 0.f);
}

// 21-tap horizontal box for 4 consecutive pixels from a smem vertical-sum row.
__device__ __forceinline__ void hbox4(const float* __restrict__ svp, int t, float* out) {
    float f[28];
#pragma unroll
    for (int j = 0; j < 7; ++j) {
        float4 v = *(const float4*)(svp + 4 * t + 4 * j);
        f[4 * j] = v.x; f[4 * j + 1] = v.y; f[4 * j + 2] = v.z; f[4 * j + 3] = v.w;
    }
    float s = 0.f;
#pragma unroll
    for (int k = 2; k <= 22; ++k) s += f[k];
    out[0] = s;
#pragma unroll
    for (int c = 1; c < 4; ++c) { s += f[22 + c] - f[1 + c]; out[c] = s; }
}

// ---------------------------------------------------------------------------
// Phase 1 (khA): fused vertical+horizontal box + reduction for {mask,b,b^2}.
// Block = 128 thr, 512-px strip x SEG rows. grid (4, HH/SEG) = 1024 blocks.
// ---------------------------------------------------------------------------
__global__ void __launch_bounds__(128) khA(const float4* __restrict__ I4,
                                           const float4* __restrict__ e4,
                                           const float4* __restrict__ u4,
                                           const float4* __restrict__ B4) {
    __shared__ __align__(16) float sv[2][3][SVW];
    __shared__ float sred[32];
    int t = threadIdx.x;
    int bx = blockIdx.x;
    int r0 = blockIdx.y * SEG;
    int c = bx * 128 + t;
    bool hasHalo = t < 6;
    int hc = bx * 128 + ((t < 3) ? t - 3 : 125 + t);
    bool hValid = hasHalo && ((unsigned)hc < (unsigned)W4);
    int hoff = (t < 3) ? 4 * t : 524 + 4 * (t - 3);

    float4 sm = f4z(), sb = f4z(), sb2 = f4z();
    float4 hm = f4z(), hb = f4z(), hb2 = f4z();
    for (int y = r0 - RAD; y <= r0 + RAD; ++y) {
        if (y >= 0 && y < HH) {
            float4 iv = __ldg(I4 + y * W4 + c);
            float4 bv = __ldg(B4 + y * W4 + c);
            sm = f4add(sm, f4mask(iv));
            sb = f4add(sb, bv);
            sb2 = f4add(sb2, f4mul(bv, bv));
            if (hValid) {
                float4 ih = __ldg(I4 + y * W4 + hc);
                float4 bh = __ldg(B4 + y * W4 + hc);
                hm = f4add(hm, f4mask(ih));
                hb = f4add(hb, bh);
                hb2 = f4add(hb2, f4mul(bh, bh));
            }
        }
    }

    float a[8] = {0, 0, 0, 0, 0, 0, 0, 0};
#pragma unroll 2
    for (int i = 0; i < SEG; ++i) {
        int y = r0 + i;
        int buf = i & 1;
        *(float4*)&sv[buf][0][12 + 4 * t] = sm;
        *(float4*)&sv[buf][1][12 + 4 * t] = sb;
        *(float4*)&sv[buf][2][12 + 4 * t] = sb2;
        if (hasHalo) {
            *(float4*)&sv[buf][0][hoff] = hm;
            *(float4*)&sv[buf][1][hoff] = hb;
            *(float4*)&sv[buf][2][hoff] = hb2;
        }
        __syncthreads();

        float nrm[4], bk[4], b2k[4];
        hbox4(sv[buf][0], t, nrm);
        hbox4(sv[buf][1], t, bk);
        hbox4(sv[buf][2], t, b2k);

        int g = y * W4 + c;
        float4 Iv = __ldg(I4 + g), ev = __ldg(e4 + g);
        float4 U0 = __ldg(u4 + g), U1 = __ldg(u4 + HWN4 + g);
        float4 U2 = __ldg(u4 + 2 * HWN4 + g), U3 = __ldg(u4 + 3 * HWN4 + g);
        const float* fI = (const float*)&Iv;
        const float* fe = (const float*)&ev;
        const float* f0 = (const float*)&U0;
        const float* f1 = (const float*)&U1;
        const float* f2 = (const float*)&U2;
        const float* f3 = (const float*)&U3;
#pragma unroll
        for (int k = 0; k < 4; ++k) {
            float inv = 1.f / (nrm[k] + EPSF);
            float bKc = bk[k] * inv;
            float b2Kc = b2k[k] * inv;
            float p0 = f0[k] * f0[k], p1 = f1[k] * f1[k];
            float p2 = f2[k] * f2[k], p3 = f3[k] * f3[k];
            float A = (fI[k] - fe[k]) * bKc;
            a[0] += fI[k] * p0; a[1] += p0;
            a[2] += A * p1;  a[3] += A * p2;  a[4] += A * p3;
            a[5] += b2Kc * p1; a[6] += b2Kc * p2; a[7] += b2Kc * p3;
        }

        int ya = y + RAD + 1, yr = y - RAD;
        if (ya < HH) {
            float4 iv2 = __ldg(I4 + ya * W4 + c);
            float4 bv2 = __ldg(B4 + ya * W4 + c);
            sm = f4add(sm, f4mask(iv2));
            sb = f4add(sb, bv2);
            sb2 = f4add(sb2, f4mul(bv2, bv2));
        }
        if (yr >= 0) {
            float4 iv2 = __ldg(I4 + yr * W4 + c);
            float4 bv2 = __ldg(B4 + yr * W4 + c);
            sm = f4sub(sm, f4mask(iv2));
            sb = f4sub(sb, bv2);
            sb2 = f4sub(sb2, f4mul(bv2, bv2));
        }
        if (hValid) {
            if (ya < HH) {
                float4 ih = __ldg(I4 + ya * W4 + hc);
                float4 bh = __ldg(B4 + ya * W4 + hc);
                hm = f4add(hm, f4mask(ih));
                hb = f4add(hb, bh);
                hb2 = f4add(hb2, f4mul(bh, bh));
            }
            if (yr >= 0) {
                float4 ih = __ldg(I4 + yr * W4 + hc);
                float4 bh = __ldg(B4 + yr * W4 + hc);
                hm = f4sub(hm, f4mask(ih));
                hb = f4sub(hb, bh);
                hb2 = f4sub(hb2, f4mul(bh, bh));
            }
        }
    }

    int lane = t & 31, w = t >> 5;
#pragma unroll
    for (int ch = 0; ch < 8; ++ch) {
        float v = a[ch];
#pragma unroll
        for (int off = 16; off; off >>= 1) v += __shfl_down_sync(0xffffffffu, v, off);
        if (lane == 0) sred[w * 8 + ch] = v;
    }
    __syncthreads();
    if (t < 8) {
        double s = 0;
#pragma unroll
        for (int ww2 = 0; ww2 < 4; ++ww2) s += (double)sred[ww2 * 8 + t];
        atomicAdd(&g_acc[t], s);
    }
    __syncthreads();
    if (t == 0) {
        __threadfence();
        unsigned tk = atomicAdd(&g_tickA, 1u);
        if (tk == gridDim.x * gridDim.y - 1) {
            double tot[8];
#pragma unroll
            for (int ch = 0; ch < 8; ++ch) tot[ch] = atomicAdd(&g_acc[ch], 0.0);
            g_v[0] = (float)(tot[0] / (tot[1] + 1e-9));
            g_v[1] = (float)(tot[2] / (tot[5] + 1e-9));
            g_v[2] = (float)(tot[3] / (tot[6] + 1e-9));
            g_v[3] = (float)(tot[4] / (tot[7] + 1e-9));
#pragma unroll
            for (int ch = 0; ch < 8; ++ch) g_acc[ch] = 0.0;
            g_tickA = 0u;
        }
    }
}

// ---------------------------------------------------------------------------
// Phase 2 (khB): fused vertical+horizontal box of {mask(I), S1, S2} where
// S1=(I-e)*sum(v*u^2), S2=sum(v^2*u^2) are computed on the fly (window rows
// come from L2). Masked combine + loss. Last block writes d_out.
// ---------------------------------------------------------------------------
struct Trip { float4 m, s1, s2; };

__device__ __forceinline__ Trip compT(const float4* __restrict__ I4,
                                      const float4* __restrict__ e4,
                                      const float4* __restrict__ u4, int o,
                                      float v0, float v1, float v2, float v3,
                                      float w0, float w1, float w2, float w3) {
    Trip r;
    float4 Iv = __ldg(I4 + o), ev = __ldg(e4 + o);
    float4 U0 = __ldg(u4 + o), U1 = __ldg(u4 + HWN4 + o);
    float4 U2 = __ldg(u4 + 2 * HWN4 + o), U3 = __ldg(u4 + 3 * HWN4 + o);
    float4 P0 = f4mul(U0, U0), P1 = f4mul(U1, U1);
    float4 P2 = f4mul(U2, U2), P3 = f4mul(U3, U3);
    r.m = f4mask(Iv);
    r.s1.x = (Iv.x - ev.x) * (v0 * P0.x + v1 * P1.x + v2 * P2.x + v3 * P3.x);
    r.s1.y = (Iv.y - ev.y) * (v0 * P0.y + v1 * P1.y + v2 * P2.y + v3 * P3.y);
    r.s1.z = (Iv.z - ev.z) * (v0 * P0.z + v1 * P1.z + v2 * P2.z + v3 * P3.z);
    r.s1.w = (Iv.w - ev.w) * (v0 * P0.w + v1 * P1.w + v2 * P2.w + v3 * P3.w);
    r.s2.x = w0 * P0.x + w1 * P1.x + w2 * P2.x + w3 * P3.x;
    r.s2.y = w0 * P0.y + w1 * P1.y + w2 * P2.y + w3 * P3.y;
    r.s2.z = w0 * P0.z + w1 * P1.z + w2 * P2.z + w3 * P3.z;
    r.s2.w = w0 * P0.w + w1 * P1.w + w2 * P2.w + w3 * P3.w;
    return r;
}

__global__ void __launch_bounds__(128) khB(const float4* __restrict__ I4,
                                           const float4* __restrict__ e4,
                                           const float4* __restrict__ u4,
                                           const float4* __restrict__ B4,
                                           float* __restrict__ out) {
    __shared__ __align__(16) float sv[2][3][SVW];
    __shared__ double swred[4];
    int t = threadIdx.x;
    int bx = blockIdx.x;
    int r0 = blockIdx.y * SEG;
    int c = bx * 128 + t;
    bool hasHalo = t < 6;
    int hc = bx * 128 + ((t < 3) ? t - 3 : 125 + t);
    bool hValid = hasHalo && ((unsigned)hc < (unsigned)W4);
    int hoff = (t < 3) ? 4 * t : 524 + 4 * (t - 3);

    float v0 = g_v[0], v1 = g_v[1], v2 = g_v[2], v3 = g_v[3];
    float w0 = v0 * v0, w1 = v1 * v1, w2 = v2 * v2, w3 = v3 * v3;

    float4 sm = f4z(), s1 = f4z(), s2 = f4z();
    float4 hm = f4z(), h1 = f4z(), h2 = f4z();
    for (int y = r0 - RAD; y <= r0 + RAD; ++y) {
        if (y >= 0 && y < HH) {
            Trip p = compT(I4, e4, u4, y * W4 + c, v0, v1, v2, v3, w0, w1, w2, w3);
            sm = f4add(sm, p.m); s1 = f4add(s1, p.s1); s2 = f4add(s2, p.s2);
            if (hValid) {
                Trip q = compT(I4, e4, u4, y * W4 + hc, v0, v1, v2, v3, w0, w1, w2, w3);
                hm = f4add(hm, q.m); h1 = f4add(h1, q.s1); h2 = f4add(h2, q.s2);
            }
        }
    }

    float acc = 0.f;
#pragma unroll 2
    for (int i = 0; i < SEG; ++i) {
        int y = r0 + i;
        int buf = i & 1;
        *(float4*)&sv[buf][0][12 + 4 * t] = sm;
        *(float4*)&sv[buf][1][12 + 4 * t] = s1;
        *(float4*)&sv[buf][2][12 + 4 * t] = s2;
        if (hasHalo) {
            *(float4*)&sv[buf][0][hoff] = hm;
            *(float4*)&sv[buf][1][hoff] = h1;
            *(float4*)&sv[buf][2][hoff] = h2;
        }
        __syncthreads();

        float nrm[4], bd[4], db[4];
        hbox4(sv[buf][0], t, nrm);
        hbox4(sv[buf][1], t, bd);
        hbox4(sv[buf][2], t, db);

        int g = y * W4 + c;
        float4 Iv = __ldg(I4 + g), Bv = __ldg(B4 + g);
        const float* fI = (const float*)&Iv;
        const float* fB = (const float*)&Bv;
#pragma unroll
        for (int k = 0; k < 4; ++k) {
            float inv = 1.f / (nrm[k] + EPSF);
            float bdc = bd[k] * inv;
            float dbc = db[k] * inv;
            float m = (fI[k] > THR) ? 1.f : 0.f;
            bdc = bdc * m + (1.f - m);
            dbc = dbc * m + (1.f - m);
            float bn = bdc / (dbc + EPSF);
            float d = fB[k] - bn;
            acc += d * d;
        }

        int ya = y + RAD + 1, yr = y - RAD;
        if (ya < HH) {
            Trip p = compT(I4, e4, u4, ya * W4 + c, v0, v1, v2, v3, w0, w1, w2, w3);
            sm = f4add(sm, p.m); s1 = f4add(s1, p.s1); s2 = f4add(s2, p.s2);
        }
        if (yr >= 0) {
            Trip p = compT(I4, e4, u4, yr * W4 + c, v0, v1, v2, v3, w0, w1, w2, w3);
            sm = f4sub(sm, p.m); s1 = f4sub(s1, p.s1); s2 = f4sub(s2, p.s2);
        }
        if (hValid) {
            if (ya < HH) {
                Trip q = compT(I4, e4, u4, ya * W4 + hc, v0, v1, v2, v3, w0, w1, w2, w3);
                hm = f4add(hm, q.m); h1 = f4add(h1, q.s1); h2 = f4add(h2, q.s2);
            }
            if (yr >= 0) {
                Trip q = compT(I4, e4, u4, yr * W4 + hc, v0, v1, v2, v3, w0, w1, w2, w3);
                hm = f4sub(hm, q.m); h1 = f4sub(h1, q.s1); h2 = f4sub(h2, q.s2);
            }
        }
    }

    int lane = t & 31, w = t >> 5;
#pragma unroll
    for (int off = 16; off; off >>= 1) acc += __shfl_down_sync(0xffffffffu, acc, off);
    if (lane == 0) swred[w] = (double)acc;
    __syncthreads();
    if (t == 0) {
        double s = swred[0] + swred[1] + swred[2] + swred[3];
        atomicAdd(&g_loss, s);
        __threadfence();
        unsigned tk = atomicAdd(&g_tickB, 1u);
        if (tk == gridDim.x * gridDim.y - 1) {
            double tot = atomicAdd(&g_loss, 0.0);
            out[0] = (float)(tot / (double)HWN);
            g_loss = 0.0;
            g_tickB = 0u;
        }
    }
}

// ---------------------------------------------------------------------------
extern "C" void kernel_launch(void* const* d_in, const int* in_sizes, int n_in,
                              void* d_out, int out_size) {
    (void)in_sizes; (void)n_in; (void)out_size;
    const float4* I = (const float4*)d_in[0];
    const float4* u = (const float4*)d_in[1];
    const float4* b = (const float4*)d_in[2];
    const float4* e = (const float4*)d_in[3];

    dim3 gs(W4 / 128, HH / SEG);   // (4, 256) = 1024 blocks

    khA<<<gs, 128>>>(I, e, u, b);
    khB<<<gs, 128>>>(I, e, u, b, (float*)d_out);
}

// round 7
// speedup vs baseline: 1.1021x; 1.1021x over previous
#include <cuda_runtime.h>

#define HH 2048
#define WW 2048
#define W4 (WW/4)
#define HWN (HH*WW)
#define HWN4 (HWN/4)
#define RAD 10
#define SEG 8
#define THR 1e-3f
#define EPSF 1e-9f
#define WR 152   // per-warp smem row: 12 halo + 128 + 12 halo floats

__device__ float g_S1[HWN];        // elementwise S1 (dense)
__device__ float g_S2[HWN];        // elementwise S2 (dense)
__device__ double g_acc[8];        // phase-1 reduction channels (self-resetting)
__device__ double g_loss;          // loss accumulator (self-resetting)
__device__ unsigned g_tickA;
__device__ unsigned g_tickB;
__device__ float g_v[4];

// ---- float4 helpers --------------------------------------------------------
__device__ __forceinline__ float4 f4z() { return make_float4(0.f, 0.f, 0.f, 0.f); }
__device__ __forceinline__ float4 f4add(float4 a, float4 b) {
    return make_float4(a.x + b.x, a.y + b.y, a.z + b.z, a.w + b.w);
}
__device__ __forceinline__ float4 f4sub(float4 a, float4 b) {
    return make_float4(a.x - b.x, a.y - b.y, a.z - b.z, a.w - b.w);
}
__device__ __forceinline__ float4 f4mul(float4 a, float4 b) {
    return make_float4(a.x * b.x, a.y * b.y, a.z * b.z, a.w * b.w);
}
__device__ __forceinline__ float4 f4mask(float4 i) {
    return make_float4(i.x > THR ? 1.f : 0.f, i.y > THR ? 1.f : 0.f,
                       i.z > THR ? 1.f : 0.f, i.w > THR ? 1.f : 0.f);
}

// 21-tap horizontal box for 4 consecutive pixels from a per-warp smem row.
// svp = warp's 152-float row; lane l outputs pixels at floats [12+4l .. 12+4l+3].
__device__ __forceinline__ void hbox4(const float* __restrict__ svp, int l, float* out) {
    float f[28];
#pragma unroll
    for (int j = 0; j < 7; ++j) {
        float4 v = *(const float4*)(svp + 4 * l + 4 * j);
        f[4 * j] = v.x; f[4 * j + 1] = v.y; f[4 * j + 2] = v.z; f[4 * j + 3] = v.w;
    }
    float s = 0.f;
#pragma unroll
    for (int k = 2; k <= 22; ++k) s += f[k];
    out[0] = s;
#pragma unroll
    for (int c = 1; c < 4; ++c) { s += f[22 + c] - f[1 + c]; out[c] = s; }
}

// ---------------------------------------------------------------------------
// Phase 1 (khA): fused vertical+horizontal box + reduction for {mask,b,b^2}.
// Per-warp smem halo exchange: only __syncwarp per row. grid (4, HH/SEG).
// ---------------------------------------------------------------------------
__global__ void __launch_bounds__(128) khA(const float4* __restrict__ I4,
                                           const float4* __restrict__ e4,
                                           const float4* __restrict__ u4,
                                           const float4* __restrict__ B4) {
    __shared__ __align__(16) float sv[4][3][WR];
    __shared__ float sred[32];
    int t = threadIdx.x;
    int w = t >> 5, l = t & 31;
    int bx = blockIdx.x;
    int r0 = blockIdx.y * SEG;
    int wb = bx * 128 + w * 32;      // warp's base float4 column
    int c = wb + l;                  // main column
    bool isHalo = (l < 3) | (l >= 29);
    int hc = (l < 3) ? wb - 3 + l : wb + 32 + (l - 29);
    bool hValid = isHalo && ((unsigned)hc < (unsigned)W4);
    int hoff = (l < 3) ? 4 * l : 140 + 4 * (l - 29);
    float* s0p = sv[w][0];
    float* s1p = sv[w][1];
    float* s2p = sv[w][2];

    float4 sm = f4z(), sb = f4z(), sb2 = f4z();
    float4 hm = f4z(), hb = f4z(), hb2 = f4z();
    for (int y = r0 - RAD; y <= r0 + RAD; ++y) {
        if (y >= 0 && y < HH) {
            float4 iv = __ldg(I4 + y * W4 + c);
            float4 bv = __ldg(B4 + y * W4 + c);
            sm = f4add(sm, f4mask(iv));
            sb = f4add(sb, bv);
            sb2 = f4add(sb2, f4mul(bv, bv));
            if (hValid) {
                float4 ih = __ldg(I4 + y * W4 + hc);
                float4 bh = __ldg(B4 + y * W4 + hc);
                hm = f4add(hm, f4mask(ih));
                hb = f4add(hb, bh);
                hb2 = f4add(hb2, f4mul(bh, bh));
            }
        }
    }

    float a[8] = {0, 0, 0, 0, 0, 0, 0, 0};
    for (int i = 0; i < SEG; ++i) {
        int y = r0 + i;
        *(float4*)(s0p + 12 + 4 * l) = sm;
        *(float4*)(s1p + 12 + 4 * l) = sb;
        *(float4*)(s2p + 12 + 4 * l) = sb2;
        if (isHalo) {       // hm/hb/hb2 stay zero when invalid -> correct OOB=0
            *(float4*)(s0p + hoff) = hm;
            *(float4*)(s1p + hoff) = hb;
            *(float4*)(s2p + hoff) = hb2;
        }
        __syncwarp();

        float nrm[4], bk[4], b2k[4];
        hbox4(s0p, l, nrm);
        hbox4(s1p, l, bk);
        hbox4(s2p, l, b2k);
        __syncwarp();

        int g = y * W4 + c;
        float4 Iv = __ldg(I4 + g), ev = __ldg(e4 + g);
        float4 U0 = __ldg(u4 + g), U1 = __ldg(u4 + HWN4 + g);
        float4 U2 = __ldg(u4 + 2 * HWN4 + g), U3 = __ldg(u4 + 3 * HWN4 + g);
        const float* fI = (const float*)&Iv;
        const float* fe = (const float*)&ev;
        const float* f0 = (const float*)&U0;
        const float* f1 = (const float*)&U1;
        const float* f2 = (const float*)&U2;
        const float* f3 = (const float*)&U3;
#pragma unroll
        for (int k = 0; k < 4; ++k) {
            float inv = 1.f / (nrm[k] + EPSF);
            float bKc = bk[k] * inv;
            float b2Kc = b2k[k] * inv;
            float p0 = f0[k] * f0[k], p1 = f1[k] * f1[k];
            float p2 = f2[k] * f2[k], p3 = f3[k] * f3[k];
            float A = (fI[k] - fe[k]) * bKc;
            a[0] += fI[k] * p0; a[1] += p0;
            a[2] += A * p1;  a[3] += A * p2;  a[4] += A * p3;
            a[5] += b2Kc * p1; a[6] += b2Kc * p2; a[7] += b2Kc * p3;
        }

        int ya = y + RAD + 1, yr = y - RAD;
        if (ya < HH) {
            float4 iv2 = __ldg(I4 + ya * W4 + c);
            float4 bv2 = __ldg(B4 + ya * W4 + c);
            sm = f4add(sm, f4mask(iv2));
            sb = f4add(sb, bv2);
            sb2 = f4add(sb2, f4mul(bv2, bv2));
        }
        if (yr >= 0) {
            float4 iv2 = __ldg(I4 + yr * W4 + c);
            float4 bv2 = __ldg(B4 + yr * W4 + c);
            sm = f4sub(sm, f4mask(iv2));
            sb = f4sub(sb, bv2);
            sb2 = f4sub(sb2, f4mul(bv2, bv2));
        }
        if (hValid) {
            if (ya < HH) {
                float4 ih = __ldg(I4 + ya * W4 + hc);
                float4 bh = __ldg(B4 + ya * W4 + hc);
                hm = f4add(hm, f4mask(ih));
                hb = f4add(hb, bh);
                hb2 = f4add(hb2, f4mul(bh, bh));
            }
            if (yr >= 0) {
                float4 ih = __ldg(I4 + yr * W4 + hc);
                float4 bh = __ldg(B4 + yr * W4 + hc);
                hm = f4sub(hm, f4mask(ih));
                hb = f4sub(hb, bh);
                hb2 = f4sub(hb2, f4mul(bh, bh));
            }
        }
    }

    int lane = l, wp = w;
#pragma unroll
    for (int ch = 0; ch < 8; ++ch) {
        float v = a[ch];
#pragma unroll
        for (int off = 16; off; off >>= 1) v += __shfl_down_sync(0xffffffffu, v, off);
        if (lane == 0) sred[wp * 8 + ch] = v;
    }
    __syncthreads();
    if (t < 8) {
        double s = 0;
#pragma unroll
        for (int ww2 = 0; ww2 < 4; ++ww2) s += (double)sred[ww2 * 8 + t];
        atomicAdd(&g_acc[t], s);
    }
    __syncthreads();
    if (t == 0) {
        __threadfence();
        unsigned tk = atomicAdd(&g_tickA, 1u);
        if (tk == gridDim.x * gridDim.y - 1) {
            double tot[8];
#pragma unroll
            for (int ch = 0; ch < 8; ++ch) tot[ch] = atomicAdd(&g_acc[ch], 0.0);
            g_v[0] = (float)(tot[0] / (tot[1] + 1e-9));
            g_v[1] = (float)(tot[2] / (tot[5] + 1e-9));
            g_v[2] = (float)(tot[3] / (tot[6] + 1e-9));
            g_v[3] = (float)(tot[4] / (tot[7] + 1e-9));
#pragma unroll
            for (int ch = 0; ch < 8; ++ch) g_acc[ch] = 0.0;
            g_tickA = 0u;
        }
    }
}

// ---------------------------------------------------------------------------
// K4a: elementwise S1=(I-e)*sum(v*up), S2=sum(v^2*up) — pure streaming, float4
// ---------------------------------------------------------------------------
__global__ void k4a_elem(const float4* __restrict__ I4, const float4* __restrict__ e4,
                         const float4* __restrict__ u4) {
    int idx = blockIdx.x * 256 + threadIdx.x;
    float v0 = g_v[0], v1 = g_v[1], v2 = g_v[2], v3 = g_v[3];
    float w0 = v0 * v0, w1 = v1 * v1, w2 = v2 * v2, w3 = v3 * v3;
    float4 Iv = __ldg(I4 + idx), ev = __ldg(e4 + idx);
    float4 U0 = __ldg(u4 + idx), U1 = __ldg(u4 + HWN4 + idx);
    float4 U2 = __ldg(u4 + 2 * HWN4 + idx), U3 = __ldg(u4 + 3 * HWN4 + idx);
    float4 P0 = f4mul(U0, U0), P1 = f4mul(U1, U1);
    float4 P2 = f4mul(U2, U2), P3 = f4mul(U3, U3);
    float4 s1, s2;
    s1.x = (Iv.x - ev.x) * (v0 * P0.x + v1 * P1.x + v2 * P2.x + v3 * P3.x);
    s1.y = (Iv.y - ev.y) * (v0 * P0.y + v1 * P1.y + v2 * P2.y + v3 * P3.y);
    s1.z = (Iv.z - ev.z) * (v0 * P0.z + v1 * P1.z + v2 * P2.z + v3 * P3.z);
    s1.w = (Iv.w - ev.w) * (v0 * P0.w + v1 * P1.w + v2 * P2.w + v3 * P3.w);
    s2.x = w0 * P0.x + w1 * P1.x + w2 * P2.x + w3 * P3.x;
    s2.y = w0 * P0.y + w1 * P1.y + w2 * P2.y + w3 * P3.y;
    s2.z = w0 * P0.z + w1 * P1.z + w2 * P2.z + w3 * P3.z;
    s2.w = w0 * P0.w + w1 * P1.w + w2 * P2.w + w3 * P3.w;
    ((float4*)g_S1)[idx] = s1;
    ((float4*)g_S2)[idx] = s2;
}

// ---------------------------------------------------------------------------
// Phase 2 (khB): fused vertical+horizontal box of {mask(I), S1, S2} reading
// materialized S planes. Per-warp smem, __syncwarp only. Loss -> d_out.
// ---------------------------------------------------------------------------
__global__ void __launch_bounds__(128) khB(const float4* __restrict__ I4,
                                           const float4* __restrict__ B4,
                                           float* __restrict__ out) {
    __shared__ __align__(16) float sv[4][3][WR];
    __shared__ double swred[4];
    int t = threadIdx.x;
    int w = t >> 5, l = t & 31;
    int bx = blockIdx.x;
    int r0 = blockIdx.y * SEG;
    int wb = bx * 128 + w * 32;
    int c = wb + l;
    bool isHalo = (l < 3) | (l >= 29);
    int hc = (l < 3) ? wb - 3 + l : wb + 32 + (l - 29);
    bool hValid = isHalo && ((unsigned)hc < (unsigned)W4);
    int hoff = (l < 3) ? 4 * l : 140 + 4 * (l - 29);
    float* s0p = sv[w][0];
    float* s1p = sv[w][1];
    float* s2p = sv[w][2];

    const float4* S1 = (const float4*)g_S1;
    const float4* S2 = (const float4*)g_S2;

    float4 sm = f4z(), s1 = f4z(), s2 = f4z();
    float4 hm = f4z(), h1 = f4z(), h2 = f4z();
    for (int y = r0 - RAD; y <= r0 + RAD; ++y) {
        if (y >= 0 && y < HH) {
            float4 iv = __ldg(I4 + y * W4 + c);
            sm = f4add(sm, f4mask(iv));
            s1 = f4add(s1, __ldg(S1 + y * W4 + c));
            s2 = f4add(s2, __ldg(S2 + y * W4 + c));
            if (hValid) {
                float4 ih = __ldg(I4 + y * W4 + hc);
                hm = f4add(hm, f4mask(ih));
                h1 = f4add(h1, __ldg(S1 + y * W4 + hc));
                h2 = f4add(h2, __ldg(S2 + y * W4 + hc));
            }
        }
    }

    float acc = 0.f;
    for (int i = 0; i < SEG; ++i) {
        int y = r0 + i;
        *(float4*)(s0p + 12 + 4 * l) = sm;
        *(float4*)(s1p + 12 + 4 * l) = s1;
        *(float4*)(s2p + 12 + 4 * l) = s2;
        if (isHalo) {
            *(float4*)(s0p + hoff) = hm;
            *(float4*)(s1p + hoff) = h1;
            *(float4*)(s2p + hoff) = h2;
        }
        __syncwarp();

        float nrm[4], bd[4], db[4];
        hbox4(s0p, l, nrm);
        hbox4(s1p, l, bd);
        hbox4(s2p, l, db);
        __syncwarp();

        int g = y * W4 + c;
        float4 Iv = __ldg(I4 + g), Bv = __ldg(B4 + g);
        const float* fI = (const float*)&Iv;
        const float* fB = (const float*)&Bv;
#pragma unroll
        for (int k = 0; k < 4; ++k) {
            float inv = 1.f / (nrm[k] + EPSF);
            float bdc = bd[k] * inv;
            float dbc = db[k] * inv;
            float m = (fI[k] > THR) ? 1.f : 0.f;
            bdc = bdc * m + (1.f - m);
            dbc = dbc * m + (1.f - m);
            float bn = bdc / (dbc + EPSF);
            float d = fB[k] - bn;
            acc += d * d;
        }

        int ya = y + RAD + 1, yr = y - RAD;
        if (ya < HH) {
            float4 iv2 = __ldg(I4 + ya * W4 + c);
            sm = f4add(sm, f4mask(iv2));
            s1 = f4add(s1, __ldg(S1 + ya * W4 + c));
            s2 = f4add(s2, __ldg(S2 + ya * W4 + c));
        }
        if (yr >= 0) {
            float4 iv2 = __ldg(I4 + yr * W4 + c);
            sm = f4sub(sm, f4mask(iv2));
            s1 = f4sub(s1, __ldg(S1 + yr * W4 + c));
            s2 = f4sub(s2, __ldg(S2 + yr * W4 + c));
        }
        if (hValid) {
            if (ya < HH) {
                float4 ih = __ldg(I4 + ya * W4 + hc);
                hm = f4add(hm, f4mask(ih));
                h1 = f4add(h1, __ldg(S1 + ya * W4 + hc));
                h2 = f4add(h2, __ldg(S2 + ya * W4 + hc));
            }
            if (yr >= 0) {
                float4 ih = __ldg(I4 + yr * W4 + hc);
                hm = f4sub(hm, f4mask(ih));
                h1 = f4sub(h1, __ldg(S1 + yr * W4 + hc));
                h2 = f4sub(h2, __ldg(S2 + yr * W4 + hc));
            }
        }
    }

#pragma unroll
    for (int off = 16; off; off >>= 1) acc += __shfl_down_sync(0xffffffffu, acc, off);
    if (l == 0) swred[w] = (double)acc;
    __syncthreads();
    if (t == 0) {
        double s = swred[0] + swred[1] + swred[2] + swred[3];
        atomicAdd(&g_loss, s);
        __threadfence();
        unsigned tk = atomicAdd(&g_tickB, 1u);
        if (tk == gridDim.x * gridDim.y - 1) {
            double tot = atomicAdd(&g_loss, 0.0);
            out[0] = (float)(tot / (double)HWN);
            g_loss = 0.0;
            g_tickB = 0u;
        }
    }
}

// ---------------------------------------------------------------------------
extern "C" void kernel_launch(void* const* d_in, const int* in_sizes, int n_in,
                              void* d_out, int out_size) {
    (void)in_sizes; (void)n_in; (void)out_size;
    const float4* I = (const float4*)d_in[0];
    const float4* u = (const float4*)d_in[1];
    const float4* b = (const float4*)d_in[2];
    const float4* e = (const float4*)d_in[3];

    dim3 gs(W4 / 128, HH / SEG);   // (4, 256) = 1024 blocks

    khA<<<gs, 128>>>(I, e, u, b);
    k4a_elem<<<HWN4 / 256, 256>>>(I, e, u);
    khB<<<gs, 128>>>(I, b, (float*)d_out);
}

// round 8
// speedup vs baseline: 1.3110x; 1.1895x over previous
#include <cuda_runtime.h>

#define HH 2048
#define WW 2048
#define W4 (WW/4)
#define HWN (HH*WW)
#define HWN4 (HWN/4)
#define RAD 10
#define SEG 8
#define THR 1e-3f
#define EPSF 1e-9f

// Padded horizontal layout for scratch planes: 12 zeros left, 20 zeros right.
// Device globals are zero-initialized; pads are never written -> stay zero.
#define PADL4 3                 // 12 floats
#define WP (WW + 12 + 20)       // 2080
#define WP4 (WP/4)              // 520

__device__ float g_P0[HH * WP];    // vertical box of mask (padded)
__device__ float g_P1[HH * WP];    // vertical box of b, later of S1 (padded)
__device__ float g_P2[HH * WP];    // vertical box of b*b, later of S2 (padded)
__device__ float g_S1[HWN];        // elementwise S1 (dense)
__device__ float g_S2[HWN];        // elementwise S2 (dense)
__device__ double g_acc[8];        // reduction channels (self-resetting)
__device__ double g_loss;          // loss accumulator (self-resetting)
__device__ unsigned g_tickA;
__device__ unsigned g_tickB;
__device__ float g_v[4];

// ---- float4 helpers --------------------------------------------------------
__device__ __forceinline__ float4 f4z() { return make_float4(0.f, 0.f, 0.f, 0.f); }
__device__ __forceinline__ float4 f4add(float4 a, float4 b) {
    return make_float4(a.x + b.x, a.y + b.y, a.z + b.z, a.w + b.w);
}
__device__ __forceinline__ float4 f4sub(float4 a, float4 b) {
    return make_float4(a.x - b.x, a.y - b.y, a.z - b.z, a.w - b.w);
}
__device__ __forceinline__ float4 f4mul(float4 a, float4 b) {
    return make_float4(a.x * b.x, a.y * b.y, a.z * b.z, a.w * b.w);
}
__device__ __forceinline__ float4 f4mask(float4 i) {
    return make_float4(i.x > THR ? 1.f : 0.f, i.y > THR ? 1.f : 0.f,
                       i.z > THR ? 1.f : 0.f, i.w > THR ? 1.f : 0.f);
}

// ---------------------------------------------------------------------------
// K1: vertical 21-tap box of {mask(I), b, b*b} -> padded planes.
// grid (W4/128, HH/SEG), block 128, float4 sliding window.
// ---------------------------------------------------------------------------
__global__ void k1_vert(const float4* __restrict__ I4, const float4* __restrict__ B4) {
    int col = blockIdx.x * 128 + threadIdx.x;
    int r0 = blockIdx.y * SEG;
    float4 s0 = f4z(), s1 = f4z(), s2 = f4z();
    for (int y = r0 - RAD; y <= r0 + RAD; ++y) {
        if (y >= 0 && y < HH) {
            float4 iv = __ldg(I4 + y * W4 + col);
            float4 bv = __ldg(B4 + y * W4 + col);
            s0 = f4add(s0, f4mask(iv));
            s1 = f4add(s1, bv);
            s2 = f4add(s2, f4mul(bv, bv));
        }
    }
    float4* P0 = (float4*)g_P0;
    float4* P1 = (float4*)g_P1;
    float4* P2 = (float4*)g_P2;
#pragma unroll 4
    for (int i = 0; i < SEG; ++i) {
        int y = r0 + i;
        int ya = y + RAD + 1, yr = y - RAD;
        float4 ia = f4z(), ba = f4z(), ir = f4z(), br = f4z();
        if (ya < HH) { ia = __ldg(I4 + ya * W4 + col); ba = __ldg(B4 + ya * W4 + col); }
        if (yr >= 0) { ir = __ldg(I4 + yr * W4 + col); br = __ldg(B4 + yr * W4 + col); }
        int o = y * WP4 + PADL4 + col;
        P0[o] = s0; P1[o] = s1; P2[o] = s2;
        s0 = f4add(s0, f4sub(f4mask(ia), f4mask(ir)));
        s1 = f4add(s1, f4sub(ba, br));
        s2 = f4add(s2, f4sub(f4mul(ba, ba), f4mul(br, br)));
    }
}

// ---------------------------------------------------------------------------
// Register sliding-window horizontal 21-tap box: thread t of a row produces
// outputs for pixels [8t, 8t+8). Loads 8 float4 covering logical x in
// [8t-12, 8t+20) from the padded plane. No smem, no barriers.
// ---------------------------------------------------------------------------
__device__ __forceinline__ void hbox8(const float* __restrict__ plane,
                                      int rowbase4, int t, float* out) {
    const float4* p4 = (const float4*)plane;
    float f[32];
#pragma unroll
    for (int j = 0; j < 8; ++j) {
        float4 v = __ldg(p4 + rowbase4 + 2 * t + j);
        f[4 * j] = v.x; f[4 * j + 1] = v.y; f[4 * j + 2] = v.z; f[4 * j + 3] = v.w;
    }
    float s = 0.f;
#pragma unroll
    for (int k = 2; k <= 22; ++k) s += f[k];
    out[0] = s;
#pragma unroll
    for (int i = 1; i < 8; ++i) { s += f[22 + i] - f[1 + i]; out[i] = s; }
}

// ---------------------------------------------------------------------------
// K2: horizontal box of the 3 planes (register sliding) + 8-channel reduction
// via fp64 atomics. Last block computes v[4]. One block (256 thr) per row.
// ---------------------------------------------------------------------------
__global__ void k2_hor(const float4* __restrict__ I4, const float4* __restrict__ e4,
                       const float4* __restrict__ u4) {
    __shared__ float sred[64];
    int t = threadIdx.x;
    int row = blockIdx.x;
    int rb4 = row * WP4;

    float norm[8], bK[8], b2K[8];
    hbox8(g_P0, rb4, t, norm);
    hbox8(g_P1, rb4, t, bK);
    hbox8(g_P2, rb4, t, b2K);

    float a[8] = {0, 0, 0, 0, 0, 0, 0, 0};
    int o = row * W4 + 2 * t;
#pragma unroll
    for (int h = 0; h < 2; ++h) {
        float4 Iv = __ldg(I4 + o + h), ev = __ldg(e4 + o + h);
        float4 U0 = __ldg(u4 + o + h), U1 = __ldg(u4 + HWN4 + o + h);
        float4 U2 = __ldg(u4 + 2 * HWN4 + o + h), U3 = __ldg(u4 + 3 * HWN4 + o + h);
        const float* fI = (const float*)&Iv;
        const float* fe = (const float*)&ev;
        const float* f0 = (const float*)&U0;
        const float* f1 = (const float*)&U1;
        const float* f2 = (const float*)&U2;
        const float* f3 = (const float*)&U3;
#pragma unroll
        for (int c = 0; c < 4; ++c) {
            int i = 4 * h + c;
            float inv = 1.f / (norm[i] + EPSF);
            float bKc = bK[i] * inv;
            float b2Kc = b2K[i] * inv;
            float p0 = f0[c] * f0[c], p1 = f1[c] * f1[c];
            float p2 = f2[c] * f2[c], p3 = f3[c] * f3[c];
            float A = (fI[c] - fe[c]) * bKc;
            a[0] += fI[c] * p0; a[1] += p0;
            a[2] += A * p1;  a[3] += A * p2;  a[4] += A * p3;
            a[5] += b2Kc * p1; a[6] += b2Kc * p2; a[7] += b2Kc * p3;
        }
    }
    int lane = t & 31, w = t >> 5;
#pragma unroll
    for (int c = 0; c < 8; ++c) {
        float v = a[c];
#pragma unroll
        for (int off = 16; off; off >>= 1) v += __shfl_down_sync(0xffffffffu, v, off);
        if (lane == 0) sred[w * 8 + c] = v;
    }
    __syncthreads();
    if (t < 8) {
        double s = 0;
#pragma unroll
        for (int ww2 = 0; ww2 < 8; ++ww2) s += (double)sred[ww2 * 8 + t];
        atomicAdd(&g_acc[t], s);
    }
    __syncthreads();
    if (t == 0) {
        __threadfence();
        unsigned tk = atomicAdd(&g_tickA, 1u);
        if (tk == (unsigned)(gridDim.x - 1)) {
            double tot[8];
#pragma unroll
            for (int c = 0; c < 8; ++c) tot[c] = atomicAdd(&g_acc[c], 0.0);
            g_v[0] = (float)(tot[0] / (tot[1] + 1e-9));
            g_v[1] = (float)(tot[2] / (tot[5] + 1e-9));
            g_v[2] = (float)(tot[3] / (tot[6] + 1e-9));
            g_v[3] = (float)(tot[4] / (tot[7] + 1e-9));
#pragma unroll
            for (int c = 0; c < 8; ++c) g_acc[c] = 0.0;
            g_tickA = 0u;
        }
    }
}

// ---------------------------------------------------------------------------
// K4a: elementwise S1=(I-e)*sum(v*up), S2=sum(v^2*up) — pure streaming, float4
// ---------------------------------------------------------------------------
__global__ void k4a_elem(const float4* __restrict__ I4, const float4* __restrict__ e4,
                         const float4* __restrict__ u4) {
    int idx = blockIdx.x * 256 + threadIdx.x;
    float v0 = g_v[0], v1 = g_v[1], v2 = g_v[2], v3 = g_v[3];
    float w0 = v0 * v0, w1 = v1 * v1, w2 = v2 * v2, w3 = v3 * v3;
    float4 Iv = __ldg(I4 + idx), ev = __ldg(e4 + idx);
    float4 U0 = __ldg(u4 + idx), U1 = __ldg(u4 + HWN4 + idx);
    float4 U2 = __ldg(u4 + 2 * HWN4 + idx), U3 = __ldg(u4 + 3 * HWN4 + idx);
    float4 P0 = f4mul(U0, U0), P1 = f4mul(U1, U1);
    float4 P2 = f4mul(U2, U2), P3 = f4mul(U3, U3);
    float4 s1, s2;
    s1.x = (Iv.x - ev.x) * (v0 * P0.x + v1 * P1.x + v2 * P2.x + v3 * P3.x);
    s1.y = (Iv.y - ev.y) * (v0 * P0.y + v1 * P1.y + v2 * P2.y + v3 * P3.y);
    s1.z = (Iv.z - ev.z) * (v0 * P0.z + v1 * P1.z + v2 * P2.z + v3 * P3.z);
    s1.w = (Iv.w - ev.w) * (v0 * P0.w + v1 * P1.w + v2 * P2.w + v3 * P3.w);
    s2.x = w0 * P0.x + w1 * P1.x + w2 * P2.x + w3 * P3.x;
    s2.y = w0 * P0.y + w1 * P1.y + w2 * P2.y + w3 * P3.y;
    s2.z = w0 * P0.z + w1 * P1.z + w2 * P2.z + w3 * P3.z;
    s2.w = w0 * P0.w + w1 * P1.w + w2 * P2.w + w3 * P3.w;
    ((float4*)g_S1)[idx] = s1;
    ((float4*)g_S2)[idx] = s2;
}

// ---------------------------------------------------------------------------
// K4b: vertical box of S1,S2 (dense in) -> g_P1,g_P2 (padded out)
// ---------------------------------------------------------------------------
__global__ void k4b_vert() {
    int col = blockIdx.x * 128 + threadIdx.x;
    int r0 = blockIdx.y * SEG;
    const float4* S1 = (const float4*)g_S1;
    const float4* S2 = (const float4*)g_S2;
    float4* P1 = (float4*)g_P1;
    float4* P2 = (float4*)g_P2;
    float4 s1 = f4z(), s2 = f4z();
    for (int y = r0 - RAD; y <= r0 + RAD; ++y) {
        if (y >= 0 && y < HH) {
            s1 = f4add(s1, __ldg(S1 + y * W4 + col));
            s2 = f4add(s2, __ldg(S2 + y * W4 + col));
        }
    }
#pragma unroll 4
    for (int i = 0; i < SEG; ++i) {
        int y = r0 + i;
        int ya = y + RAD + 1, yr = y - RAD;
        float4 aa = f4z(), ab = f4z(), ra = f4z(), rb = f4z();
        if (ya < HH) { aa = __ldg(S1 + ya * W4 + col); ab = __ldg(S2 + ya * W4 + col); }
        if (yr >= 0) { ra = __ldg(S1 + yr * W4 + col); rb = __ldg(S2 + yr * W4 + col); }
        int o = y * WP4 + PADL4 + col;
        P1[o] = s1; P2[o] = s2;
        s1 = f4add(s1, f4sub(aa, ra));
        s2 = f4add(s2, f4sub(ab, rb));
    }
}

// ---------------------------------------------------------------------------
// K5: horizontal box (register sliding) of {norm, S1v, S2v}; masked combine;
// loss via fp64 atomics; last block writes d_out. One block per row.
// ---------------------------------------------------------------------------
__global__ void k5_hor(const float4* __restrict__ I4, const float4* __restrict__ B4,
                       float* __restrict__ out) {
    __shared__ double sw[8];
    int t = threadIdx.x;
    int row = blockIdx.x;
    int rb4 = row * WP4;

    float norm[8], bd[8], db[8];
    hbox8(g_P0, rb4, t, norm);
    hbox8(g_P1, rb4, t, bd);
    hbox8(g_P2, rb4, t, db);

    float acc = 0.f;
    int o = row * W4 + 2 * t;
#pragma unroll
    for (int h = 0; h < 2; ++h) {
        float4 Iv = __ldg(I4 + o + h), Bv = __ldg(B4 + o + h);
        const float* fI = (const float*)&Iv;
        const float* fB = (const float*)&Bv;
#pragma unroll
        for (int c = 0; c < 4; ++c) {
            int i = 4 * h + c;
            float inv = 1.f / (norm[i] + EPSF);
            float bdc = bd[i] * inv;
            float dbc = db[i] * inv;
            float m = (fI[c] > THR) ? 1.f : 0.f;
            bdc = bdc * m + (1.f - m);
            dbc = dbc * m + (1.f - m);
            float bn = bdc / (dbc + EPSF);
            float d = fB[c] - bn;
            acc += d * d;
        }
    }
    int lane = t & 31, w = t >> 5;
#pragma unroll
    for (int off = 16; off; off >>= 1) acc += __shfl_down_sync(0xffffffffu, acc, off);
    if (lane == 0) sw[w] = (double)acc;
    __syncthreads();
    if (t == 0) {
        double s = 0;
#pragma unroll
        for (int ww2 = 0; ww2 < 8; ++ww2) s += sw[ww2];
        atomicAdd(&g_loss, s);
        __threadfence();
        unsigned tk = atomicAdd(&g_tickB, 1u);
        if (tk == (unsigned)(gridDim.x - 1)) {
            double tot = atomicAdd(&g_loss, 0.0);
            out[0] = (float)(tot / (double)HWN);
            g_loss = 0.0;
            g_tickB = 0u;
        }
    }
}

// ---------------------------------------------------------------------------
extern "C" void kernel_launch(void* const* d_in, const int* in_sizes, int n_in,
                              void* d_out, int out_size) {
    (void)in_sizes; (void)n_in; (void)out_size;
    const float4* I = (const float4*)d_in[0];
    const float4* u = (const float4*)d_in[1];
    const float4* b = (const float4*)d_in[2];
    const float4* e = (const float4*)d_in[3];

    dim3 gv(W4 / 128, HH / SEG);   // (4, 256) = 1024 blocks

    k1_vert<<<gv, 128>>>(I, b);
    k2_hor<<<HH, 256>>>(I, e, u);
    k4a_elem<<<HWN4 / 256, 256>>>(I, e, u);
    k4b_vert<<<gv, 128>>>();
    k5_hor<<<HH, 256>>>(I, b, (float*)d_out);
}